// round 16
// baseline (speedup 1.0000x reference)
#include <cuda_runtime.h>
#include <cuda_bf16.h>
#include <cuda_fp16.h>
#include <math.h>
#include <float.h>
#include <stdint.h>

#define SLEN 2048
#define HID  4096
#define NQH  32
#define NKVH 8
#define HDIM 128
#define QKVN 6144   // (32 + 2*8) * 128
#define EPSV 1e-6f
#define QBLK 128
#define NQB  (SLEN / QBLK)     // 16
#define SCALE 0.08838834764831845f
#define L2E   1.44269504088896f
#define SCL2  (0.08838834764831845f * 1.44269504088896f)   // scale * log2(e)

// ---------------- scratch (__device__ globals; no allocation) ---------------
__device__ float g_qkv[(size_t)SLEN * QKVN];                 // 50 MB
__device__ __half g_wT_hi[(size_t)QKVN * HID];               // 50 MB (weights hi only)
__device__ __half g_a_hi[(size_t)SLEN * HID];                // 16 MB
__device__ __half g_a_lo[(size_t)SLEN * HID];                // 16 MB
__device__ __nv_bfloat16 g_q_hi[(size_t)SLEN * NQH * HDIM];  // 16 MB
__device__ __nv_bfloat16 g_q_lo[(size_t)SLEN * NQH * HDIM];  // 16 MB
__device__ __nv_bfloat16 g_k_hi[(size_t)SLEN * NKVH * HDIM]; // 4 MB
__device__ __nv_bfloat16 g_k_lo[(size_t)SLEN * NKVH * HDIM]; // 4 MB
__device__ __half g_vt_hi[(size_t)NKVH * HDIM * SLEN];       // 4 MB
__device__ __half g_vt_lo[(size_t)NKVH * HDIM * SLEN];       // 4 MB

// ---------------- helpers ----------------------------------------------------
__device__ __forceinline__ uint32_t smem_to_u32(const void* p) {
    uint32_t a;
    asm("{ .reg .u64 t; cvta.to.shared.u64 t, %1; cvt.u32.u64 %0, t; }" : "=r"(a) : "l"(p));
    return a;
}
__device__ __forceinline__ void cp16(uint32_t dst, const void* src) {
    asm volatile("cp.async.cg.shared.global [%0], [%1], 16;" :: "r"(dst), "l"(src));
}
__device__ __forceinline__ void ldsm4(uint32_t& r0, uint32_t& r1, uint32_t& r2, uint32_t& r3,
                                      uint32_t addr) {
    asm volatile("ldmatrix.sync.aligned.m8n8.x4.shared.b16 {%0,%1,%2,%3}, [%4];"
        : "=r"(r0), "=r"(r1), "=r"(r2), "=r"(r3) : "r"(addr));
}
// bf16 mma (flash QK^T)
__device__ __forceinline__ void mma16816(float* c, const uint32_t* a, const uint32_t* b) {
    asm volatile(
        "mma.sync.aligned.m16n8k16.row.col.f32.bf16.bf16.f32 "
        "{%0,%1,%2,%3}, {%4,%5,%6,%7}, {%8,%9}, {%0,%1,%2,%3};"
        : "+f"(c[0]), "+f"(c[1]), "+f"(c[2]), "+f"(c[3])
        : "r"(a[0]), "r"(a[1]), "r"(a[2]), "r"(a[3]), "r"(b[0]), "r"(b[1]));
}
// fp16 mma (dense GEMMs + flash PV)
__device__ __forceinline__ void mma16816h(float* c, const uint32_t* a, const uint32_t* b) {
    asm volatile(
        "mma.sync.aligned.m16n8k16.row.col.f32.f16.f16.f32 "
        "{%0,%1,%2,%3}, {%4,%5,%6,%7}, {%8,%9}, {%0,%1,%2,%3};"
        : "+f"(c[0]), "+f"(c[1]), "+f"(c[2]), "+f"(c[3])
        : "r"(a[0]), "r"(a[1]), "r"(a[2]), "r"(a[3]), "r"(b[0]), "r"(b[1]));
}
// paired exp2 on fp16x2 (one MUFU for two elements)
__device__ __forceinline__ uint32_t ex2_f16x2(uint32_t x) {
    uint32_t r;
    asm volatile("ex2.approx.f16x2 %0, %1;" : "=r"(r) : "r"(x));
    return r;
}
__device__ __forceinline__ uint32_t packh2f(float a, float b) {
    __half2 h = __floats2half2_rn(a, b);
    return *reinterpret_cast<uint32_t*>(&h);
}
__device__ __forceinline__ float2 h2tof2(uint32_t h) {
    return __half22float2(*reinterpret_cast<__half2*>(&h));
}

// ---------------------------------------------------------------------------
// fp16x2 GEMM: C[M,N] = (Ah+Al)[M,K] * Bh[N,K]^T, fp32 accumulate.
// (unchanged from R15)
// ---------------------------------------------------------------------------
#define MM_KC 32
#define MM_ROWB 80
#define MM_TILE_BYTES (128 * MM_ROWB)          // 10240
#define MM_STAGE (3 * MM_TILE_BYTES)           // 30720 (Ah, Al, Bh)
#define MM_SMEM_TOT (2 * MM_STAGE)             // 61440

__global__ __launch_bounds__(256, 2) void gemm_fp16x2(
    const __half* __restrict__ Ahi, const __half* __restrict__ Alo,
    const __half* __restrict__ Bth,
    float* __restrict__ C, int K, int N)
{
    extern __shared__ char smem[];
    const uint32_t sbase = smem_to_u32(smem);
    const int tid = threadIdx.x;
    const int wid = tid >> 5, lane = tid & 31;
    const int wm = wid >> 1, wn = wid & 1;
    const int row0 = blockIdx.y * 128;
    const int n0 = blockIdx.x * 128;
    const int gq = lane >> 2;
    const int tq = lane & 3;
    const int l7 = lane & 7, lb8 = (lane >> 3) & 1, lb16 = (lane >> 4) & 1;

    float acc[2][8][4];
    #pragma unroll
    for (int mt = 0; mt < 2; mt++)
        #pragma unroll
        for (int nt = 0; nt < 8; nt++)
            #pragma unroll
            for (int i = 0; i < 4; i++)
                acc[mt][nt][i] = 0.f;

    const int NCH = K / MM_KC;

    auto fill = [&](int s, int c) {
        const uint32_t sb = sbase + s * MM_STAGE;
        const int k0 = c * MM_KC;
        #pragma unroll
        for (int i = 0; i < 2; i++) {
            int idx = i * 256 + tid;
            int r = idx >> 2;
            int seg = idx & 3;
            uint32_t dst = sb + r * MM_ROWB + seg * 16;
            size_t ao = (size_t)(row0 + r) * K + k0 + seg * 8;
            size_t bo = (size_t)(n0 + r) * K + k0 + seg * 8;
            cp16(dst,                      Ahi + ao);
            cp16(dst + MM_TILE_BYTES,      Alo + ao);
            cp16(dst + 2 * MM_TILE_BYTES,  Bth + bo);
        }
        asm volatile("cp.async.commit_group;");
    };

    fill(0, 0);

    for (int c = 0; c < NCH; c++) {
        if (c + 1 < NCH) {
            fill((c + 1) & 1, c + 1);
            asm volatile("cp.async.wait_group 1;");
        } else {
            asm volatile("cp.async.wait_group 0;");
        }
        __syncthreads();

        const uint32_t sb = sbase + (c & 1) * MM_STAGE;
        #pragma unroll
        for (int ks = 0; ks < MM_KC / 16; ks++) {
            uint32_t ah[2][4], al[2][4];
            #pragma unroll
            for (int mt = 0; mt < 2; mt++) {
                uint32_t aaddr = sb + (uint32_t)((wm * 32 + mt * 16 + l7 + lb8 * 8) * MM_ROWB
                               + ks * 32 + lb16 * 16);
                ldsm4(ah[mt][0], ah[mt][1], ah[mt][2], ah[mt][3], aaddr);
                ldsm4(al[mt][0], al[mt][1], al[mt][2], al[mt][3], aaddr + MM_TILE_BYTES);
            }
            #pragma unroll
            for (int t = 0; t < 4; t++) {
                uint32_t baddr = sb + 2 * MM_TILE_BYTES
                               + (uint32_t)((wn * 64 + t * 16 + lb16 * 8 + l7) * MM_ROWB
                               + ks * 32 + lb8 * 16);
                uint32_t bh[4];
                ldsm4(bh[0], bh[1], bh[2], bh[3], baddr);
                #pragma unroll
                for (int mt = 0; mt < 2; mt++) {
                    mma16816h(acc[mt][2 * t],     ah[mt], bh + 0);
                    mma16816h(acc[mt][2 * t],     al[mt], bh + 0);
                    mma16816h(acc[mt][2 * t + 1], ah[mt], bh + 2);
                    mma16816h(acc[mt][2 * t + 1], al[mt], bh + 2);
                }
            }
        }
        __syncthreads();
    }

    #pragma unroll
    for (int mt = 0; mt < 2; mt++) {
        int r = row0 + wm * 32 + mt * 16 + gq;
        #pragma unroll
        for (int nt = 0; nt < 8; nt++) {
            int cc = n0 + wn * 64 + nt * 8 + tq * 2;
            *reinterpret_cast<float2*>(&C[(size_t)r * N + cc]) =
                make_float2(acc[mt][nt][0], acc[mt][nt][1]);
            *reinterpret_cast<float2*>(&C[(size_t)(r + 8) * N + cc]) =
                make_float2(acc[mt][nt][2], acc[mt][nt][3]);
        }
    }
}

// ---------------------------------------------------------------------------
// Fused flash attention: QK^T bf16x3, softmax via ex2.approx.f16x2
// (log2-domain, half the MUFU ops), PV fp16 (P from ex2, V hi+lo).
// ---------------------------------------------------------------------------
#define FA_ROWB 272
#define FA_TILE (128 * FA_ROWB)     // 34816
#define FA_QHI  0
#define FA_QLO  (1 * FA_TILE)
#define FA_KHI  (2 * FA_TILE)
#define FA_KLO  (3 * FA_TILE)
#define FA_VHI  (4 * FA_TILE)
#define FA_VLO  (5 * FA_TILE)
#define FA_SMEM (6 * FA_TILE)       // 208896

__global__ __launch_bounds__(256, 1) void flash_attn(
    const __nv_bfloat16* __restrict__ qhi, const __nv_bfloat16* __restrict__ qlo,
    const __nv_bfloat16* __restrict__ khi, const __nv_bfloat16* __restrict__ klo,
    const __half* __restrict__ vthi, const __half* __restrict__ vtlo,
    __half* __restrict__ outhi, __half* __restrict__ outlo)
{
    extern __shared__ char smem[];
    const uint32_t sb = smem_to_u32(smem);
    const int tid = threadIdx.x;
    const int wid = tid >> 5, lane = tid & 31;
    const int gq = lane >> 2, tq = lane & 3;
    const int l7 = lane & 7, lb8 = (lane >> 3) & 1, lb16 = (lane >> 4) & 1;
    const int qb = (NQB - 1) - blockIdx.x;       // long blocks first
    const int h = blockIdx.y;
    const int kh = h >> 2;                       // GQA: 4 q-heads per kv-head
    const int r0 = qb * QBLK;
    const int wrow = wid * 16;

    // ---- Q tile load (once), fully waited before use ----
    {
        const __nv_bfloat16* srcH = qhi + ((size_t)r0 * NQH + h) * HDIM;
        const __nv_bfloat16* srcL = qlo + ((size_t)r0 * NQH + h) * HDIM;
        #pragma unroll
        for (int i = 0; i < 8; i++) {
            int idx = i * 256 + tid;
            int r = idx >> 4, seg = idx & 15;
            size_t so = (size_t)r * (NQH * HDIM) + seg * 8;
            uint32_t dst = sb + r * FA_ROWB + seg * 16;
            cp16(dst + FA_QHI, srcH + so);
            cp16(dst + FA_QLO, srcL + so);
        }
        asm volatile("cp.async.commit_group;");
        asm volatile("cp.async.wait_group 0;");
    }
    __syncthreads();

    float m0 = -1e30f, m1 = -1e30f, l0 = 0.f, l1 = 0.f;
    float o[16][4];
    #pragma unroll
    for (int nt = 0; nt < 16; nt++)
        #pragma unroll
        for (int i = 0; i < 4; i++) o[nt][i] = 0.f;

    for (int j = 0; j <= qb; j++) {
        const int t0 = j * QBLK;
        // ---- K group, then V group ----
        {
            const __nv_bfloat16* srcH = khi + ((size_t)t0 * NKVH + kh) * HDIM;
            const __nv_bfloat16* srcL = klo + ((size_t)t0 * NKVH + kh) * HDIM;
            #pragma unroll
            for (int i = 0; i < 8; i++) {
                int idx = i * 256 + tid;
                int r = idx >> 4, seg = idx & 15;
                size_t so = (size_t)r * (NKVH * HDIM) + seg * 8;
                uint32_t dst = sb + r * FA_ROWB + seg * 16;
                cp16(dst + FA_KHI, srcH + so);
                cp16(dst + FA_KLO, srcL + so);
            }
            asm volatile("cp.async.commit_group;");
            const __half* svH = vthi + (size_t)kh * HDIM * SLEN + t0;
            const __half* svL = vtlo + (size_t)kh * HDIM * SLEN + t0;
            #pragma unroll
            for (int i = 0; i < 8; i++) {
                int idx = i * 256 + tid;
                int r = idx >> 4, seg = idx & 15;
                size_t so = (size_t)r * SLEN + seg * 8;
                uint32_t dst = sb + r * FA_ROWB + seg * 16;
                cp16(dst + FA_VHI, svH + so);
                cp16(dst + FA_VLO, svL + so);
            }
            asm volatile("cp.async.commit_group;");
        }
        asm volatile("cp.async.wait_group 1;");   // K ready; V may be in flight
        __syncthreads();

        // ---- S = Q K^T (bf16x3) ----
        float s[16][4];
        #pragma unroll
        for (int nt = 0; nt < 16; nt++)
            #pragma unroll
            for (int i = 0; i < 4; i++) s[nt][i] = 0.f;

        #pragma unroll
        for (int ks = 0; ks < 8; ks++) {
            uint32_t aaddr = sb + FA_QHI
                           + (uint32_t)((wrow + l7 + lb8 * 8) * FA_ROWB + ks * 32 + lb16 * 16);
            uint32_t ah[4], al[4];
            ldsm4(ah[0], ah[1], ah[2], ah[3], aaddr);
            ldsm4(al[0], al[1], al[2], al[3], aaddr + FA_TILE);
            #pragma unroll
            for (int t = 0; t < 8; t++) {
                uint32_t kaddr = sb + FA_KHI
                               + (uint32_t)((t * 16 + lb16 * 8 + l7) * FA_ROWB + ks * 32 + lb8 * 16);
                uint32_t bh[4], bl[4];
                ldsm4(bh[0], bh[1], bh[2], bh[3], kaddr);
                ldsm4(bl[0], bl[1], bl[2], bl[3], kaddr + FA_TILE);
                mma16816(s[2 * t],     ah, bh + 0);
                mma16816(s[2 * t],     ah, bl + 0);
                mma16816(s[2 * t],     al, bh + 0);
                mma16816(s[2 * t + 1], ah, bh + 2);
                mma16816(s[2 * t + 1], ah, bl + 2);
                mma16816(s[2 * t + 1], al, bh + 2);
            }
        }

        // ---- scale into log2 domain + causal mask (diagonal block only) ----
        #pragma unroll
        for (int nt = 0; nt < 16; nt++)
            #pragma unroll
            for (int i = 0; i < 4; i++) s[nt][i] *= SCL2;
        if (j == qb) {
            const int lr0 = wrow + gq, lr1 = lr0 + 8;
            #pragma unroll
            for (int nt = 0; nt < 16; nt++) {
                int c0 = nt * 8 + tq * 2;
                if (c0 > lr0)     s[nt][0] = -1e30f;
                if (c0 + 1 > lr0) s[nt][1] = -1e30f;
                if (c0 > lr1)     s[nt][2] = -1e30f;
                if (c0 + 1 > lr1) s[nt][3] = -1e30f;
            }
        }

        // ---- online softmax (log2 domain; quad-level row reductions) ----
        float rm0 = -1e30f, rm1 = -1e30f;
        #pragma unroll
        for (int nt = 0; nt < 16; nt++) {
            rm0 = fmaxf(rm0, fmaxf(s[nt][0], s[nt][1]));
            rm1 = fmaxf(rm1, fmaxf(s[nt][2], s[nt][3]));
        }
        rm0 = fmaxf(rm0, __shfl_xor_sync(0xffffffffu, rm0, 1));
        rm0 = fmaxf(rm0, __shfl_xor_sync(0xffffffffu, rm0, 2));
        rm1 = fmaxf(rm1, __shfl_xor_sync(0xffffffffu, rm1, 1));
        rm1 = fmaxf(rm1, __shfl_xor_sync(0xffffffffu, rm1, 2));
        float mn0 = fmaxf(m0, rm0), mn1 = fmaxf(m1, rm1);
        float al0 = exp2f(m0 - mn0), al1 = exp2f(m1 - mn1);

        // ---- P = 2^(s-m) via ex2.approx.f16x2 (one MUFU per pair) ----
        float sum0 = 0.f, sum1 = 0.f;
        uint32_t pbh[16][2];
        #pragma unroll
        for (int nt = 0; nt < 16; nt++) {
            uint32_t ph01 = ex2_f16x2(packh2f(s[nt][0] - mn0, s[nt][1] - mn0));
            uint32_t ph23 = ex2_f16x2(packh2f(s[nt][2] - mn1, s[nt][3] - mn1));
            pbh[nt][0] = ph01;
            pbh[nt][1] = ph23;
            float2 p01 = h2tof2(ph01);
            float2 p23 = h2tof2(ph23);
            sum0 += p01.x + p01.y;
            sum1 += p23.x + p23.y;
        }
        sum0 += __shfl_xor_sync(0xffffffffu, sum0, 1);
        sum0 += __shfl_xor_sync(0xffffffffu, sum0, 2);
        sum1 += __shfl_xor_sync(0xffffffffu, sum1, 1);
        sum1 += __shfl_xor_sync(0xffffffffu, sum1, 2);
        l0 = l0 * al0 + sum0;
        l1 = l1 * al1 + sum1;
        m0 = mn0; m1 = mn1;
        #pragma unroll
        for (int nt = 0; nt < 16; nt++) {
            o[nt][0] *= al0; o[nt][1] *= al0;
            o[nt][2] *= al1; o[nt][3] *= al1;
        }

        // ---- O += Ph*Vhi + Ph*Vlo (fp16) ----
        asm volatile("cp.async.wait_group 0;");
        __syncthreads();
        #pragma unroll
        for (int kt = 0; kt < 8; kt++) {
            uint32_t ah2[4] = { pbh[2 * kt][0], pbh[2 * kt][1],
                                pbh[2 * kt + 1][0], pbh[2 * kt + 1][1] };
            #pragma unroll
            for (int t = 0; t < 8; t++) {
                uint32_t vaddr = sb + FA_VHI
                               + (uint32_t)((t * 16 + lb16 * 8 + l7) * FA_ROWB + kt * 32 + lb8 * 16);
                uint32_t bh[4], bl[4];
                ldsm4(bh[0], bh[1], bh[2], bh[3], vaddr);
                ldsm4(bl[0], bl[1], bl[2], bl[3], vaddr + FA_TILE);
                mma16816h(o[2 * t],     ah2, bh + 0);
                mma16816h(o[2 * t],     ah2, bl + 0);
                mma16816h(o[2 * t + 1], ah2, bh + 2);
                mma16816h(o[2 * t + 1], ah2, bl + 2);
            }
        }
        __syncthreads();   // all K/V reads done before next iter overwrites
    }

    // ---- epilogue: normalize + split to fp16 hi/lo ----
    const float inv0 = 1.f / fmaxf(l0, 1e-20f);
    const float inv1 = 1.f / fmaxf(l1, 1e-20f);
    const int grow0 = r0 + wrow + gq, grow1 = grow0 + 8;
    #pragma unroll
    for (int nt = 0; nt < 16; nt++) {
        int c = h * HDIM + nt * 8 + tq * 2;
        float f0 = o[nt][0] * inv0, f1 = o[nt][1] * inv0;
        float f2 = o[nt][2] * inv1, f3 = o[nt][3] * inv1;
        __half h0 = __float2half_rn(f0), h1 = __float2half_rn(f1);
        __half h2 = __float2half_rn(f2), h3 = __float2half_rn(f3);
        __half e0 = __float2half_rn(f0 - __half2float(h0));
        __half e1 = __float2half_rn(f1 - __half2float(h1));
        __half e2 = __float2half_rn(f2 - __half2float(h2));
        __half e3 = __float2half_rn(f3 - __half2float(h3));
        *reinterpret_cast<__half2*>(&outhi[(size_t)grow0 * HID + c]) = __half2(h0, h1);
        *reinterpret_cast<__half2*>(&outlo[(size_t)grow0 * HID + c]) = __half2(e0, e1);
        *reinterpret_cast<__half2*>(&outhi[(size_t)grow1 * HID + c]) = __half2(h2, h3);
        *reinterpret_cast<__half2*>(&outlo[(size_t)grow1 * HID + c]) = __half2(e2, e3);
    }
}

// ---------------------------------------------------------------------------
// RMSNorm + RoPE -> bf16 hi/lo Q and K (unchanged).
// ---------------------------------------------------------------------------
__global__ __launch_bounds__(128) void rmsnorm_rope_split(
    const float* __restrict__ cosT, const float* __restrict__ sinT,
    const float* __restrict__ q_gamma, const float* __restrict__ k_gamma,
    __nv_bfloat16* __restrict__ qhi, __nv_bfloat16* __restrict__ qlo,
    __nv_bfloat16* __restrict__ khi, __nv_bfloat16* __restrict__ klo)
{
    const int s = blockIdx.x;
    const int h = blockIdx.y;           // 0..39
    const float* x;
    const float* gamma;
    __nv_bfloat16 *dh, *dl;
    if (h < NQH) {
        x = g_qkv + (size_t)s * QKVN + h * HDIM;
        gamma = q_gamma;
        dh = qhi + ((size_t)s * NQH + h) * HDIM;
        dl = qlo + ((size_t)s * NQH + h) * HDIM;
    } else {
        x = g_qkv + (size_t)s * QKVN + NQH * HDIM + (h - NQH) * HDIM;
        gamma = k_gamma;
        dh = khi + ((size_t)s * NKVH + (h - NQH)) * HDIM;
        dl = klo + ((size_t)s * NKVH + (h - NQH)) * HDIM;
    }

    const int tid = threadIdx.x;
    float v = x[tid];
    float sq = v * v;
    #pragma unroll
    for (int o = 16; o > 0; o >>= 1) sq += __shfl_xor_sync(0xffffffffu, sq, o);
    __shared__ float ws[4];
    if ((tid & 31) == 0) ws[tid >> 5] = sq;
    __syncthreads();
    float total = ws[0] + ws[1] + ws[2] + ws[3];
    float rinv = rsqrtf(total * (1.0f / HDIM) + EPSV);

    __shared__ float xn[HDIM];
    xn[tid] = v * rinv * gamma[tid];
    __syncthreads();

    if (tid < 64) {
        float c = cosT[(size_t)s * 64 + tid];
        float sn = sinT[(size_t)s * 64 + tid];
        float x1 = xn[tid];
        float x2 = xn[tid + 64];
        float y1 = x1 * c - x2 * sn;
        float y2 = x2 * c + x1 * sn;
        __nv_bfloat16 h1 = __float2bfloat16(y1);
        __nv_bfloat16 h2 = __float2bfloat16(y2);
        dh[tid] = h1;
        dh[tid + 64] = h2;
        dl[tid] = __float2bfloat16(y1 - __bfloat162float(h1));
        dl[tid + 64] = __float2bfloat16(y2 - __bfloat162float(h2));
    }
}

// ---------------------------------------------------------------------------
// V: fp32 [seq][kvh*128 cols] -> transposed fp16 hi/lo [kvh][d][seq]
// ---------------------------------------------------------------------------
__global__ __launch_bounds__(256) void v_split_transpose(
    __half* __restrict__ TH, __half* __restrict__ TL)
{
    __shared__ float t[32][33];
    const int t0 = blockIdx.x * 32;
    const int d0 = blockIdx.y * 32;
    const int kh = blockIdx.z;
    const int tx = threadIdx.x & 31, ty = threadIdx.x >> 5;
    #pragma unroll
    for (int i = 0; i < 4; i++)
        t[ty + 8 * i][tx] =
            g_qkv[(size_t)(t0 + ty + 8 * i) * QKVN + (NQH + NKVH) * HDIM + kh * HDIM + d0 + tx];
    __syncthreads();
    #pragma unroll
    for (int i = 0; i < 4; i++) {
        float x = t[tx][ty + 8 * i];
        __half h = __float2half_rn(x);
        size_t o = ((size_t)kh * HDIM + d0 + ty + 8 * i) * SLEN + t0 + tx;
        TH[o] = h;
        TL[o] = __float2half_rn(x - __half2float(h));
    }
}

// ---------------------------------------------------------------------------
// fp32 -> fp16 hi/lo split (elementwise)
// ---------------------------------------------------------------------------
__global__ void split_rows_kernel(const float* __restrict__ X,
                                  __half* __restrict__ H,
                                  __half* __restrict__ L, int n)
{
    int i = blockIdx.x * blockDim.x + threadIdx.x;
    if (i < n) {
        float x = X[i];
        __half h = __float2half_rn(x);
        H[i] = h;
        L[i] = __float2half_rn(x - __half2float(h));
    }
}

// fp32 [K,N] -> transposed fp16 hi [N,K] (weights: hi only)
__global__ __launch_bounds__(256) void split_transpose_kernel(
    const float* __restrict__ W, __half* __restrict__ TH, int K, int N)
{
    __shared__ float t[32][33];
    const int n0 = blockIdx.x * 32, k0 = blockIdx.y * 32;
    const int tx = threadIdx.x & 31, ty = threadIdx.x >> 5;
    #pragma unroll
    for (int i = 0; i < 4; i++)
        t[ty + 8 * i][tx] = W[(size_t)(k0 + ty + 8 * i) * N + n0 + tx];
    __syncthreads();
    #pragma unroll
    for (int i = 0; i < 4; i++) {
        float x = t[tx][ty + 8 * i];
        size_t o = (size_t)(n0 + ty + 8 * i) * K + k0 + tx;
        TH[o] = __float2half_rn(x);
    }
}

// ---------------------------------------------------------------------------
// launch
// ---------------------------------------------------------------------------
extern "C" void kernel_launch(void* const* d_in, const int* in_sizes, int n_in,
                              void* d_out, int out_size)
{
    (void)in_sizes; (void)n_in; (void)out_size;
    const float* hidden = (const float*)d_in[1];
    const float* Wqkv   = (const float*)d_in[2];
    const float* Wo     = (const float*)d_in[3];
    const float* qg     = (const float*)d_in[4];
    const float* kg     = (const float*)d_in[5];
    const float* cosT   = (const float*)d_in[6];
    const float* sinT   = (const float*)d_in[7];
    float* out = (float*)d_out;

    float* qkv;
    __half *wT_hi, *a_hi, *a_lo, *vt_hi, *vt_lo;
    __nv_bfloat16 *q_hi, *q_lo, *k_hi, *k_lo;
    cudaGetSymbolAddress((void**)&qkv, g_qkv);
    cudaGetSymbolAddress((void**)&wT_hi, g_wT_hi);
    cudaGetSymbolAddress((void**)&a_hi, g_a_hi);
    cudaGetSymbolAddress((void**)&a_lo, g_a_lo);
    cudaGetSymbolAddress((void**)&q_hi, g_q_hi);
    cudaGetSymbolAddress((void**)&q_lo, g_q_lo);
    cudaGetSymbolAddress((void**)&k_hi, g_k_hi);
    cudaGetSymbolAddress((void**)&k_lo, g_k_lo);
    cudaGetSymbolAddress((void**)&vt_hi, g_vt_hi);
    cudaGetSymbolAddress((void**)&vt_lo, g_vt_lo);

    cudaFuncSetAttribute(gemm_fp16x2, cudaFuncAttributeMaxDynamicSharedMemorySize, MM_SMEM_TOT);
    cudaFuncSetAttribute(flash_attn, cudaFuncAttributeMaxDynamicSharedMemorySize, FA_SMEM);

    // 1) QKV projection (fp16x2: A hi+lo, W hi)
    split_transpose_kernel<<<dim3(QKVN / 32, HID / 32), 256>>>(Wqkv, wT_hi, HID, QKVN);
    split_rows_kernel<<<(SLEN * HID + 255) / 256, 256>>>(hidden, a_hi, a_lo, SLEN * HID);
    gemm_fp16x2<<<dim3(QKVN / 128, SLEN / 128), 256, MM_SMEM_TOT>>>(
        a_hi, a_lo, wT_hi, qkv, HID, QKVN);

    // 2) RMSNorm + RoPE -> bf16 hi/lo Q, K ; V transpose+split (fp16)
    rmsnorm_rope_split<<<dim3(SLEN, NQH + NKVH), 128>>>(cosT, sinT, qg, kg,
                                                        q_hi, q_lo, k_hi, k_lo);
    v_split_transpose<<<dim3(SLEN / 32, HDIM / 32, NKVH), 256>>>(vt_hi, vt_lo);

    // 3) Fused flash attention -> a_hi/a_lo (fp16, O-proj input)
    flash_attn<<<dim3(NQB, NQH), 256, FA_SMEM>>>(
        q_hi, q_lo, k_hi, k_lo, vt_hi, vt_lo, a_hi, a_lo);

    // 4) Output projection (fp16x2)
    split_transpose_kernel<<<dim3(HID / 32, HID / 32), 256>>>(Wo, wT_hi, HID, HID);
    gemm_fp16x2<<<dim3(HID / 128, SLEN / 128), 256, MM_SMEM_TOT>>>(
        a_hi, a_lo, wT_hi, out, HID, HID);
}